// round 12
// baseline (speedup 1.0000x reference)
#include <cuda_runtime.h>
#include <cstdint>
#include <math.h>

#define BB 64
#define SEQ 512
#define HH 512
#define DD 256

// Scratch (device globals: no allocation allowed in kernel_launch)
__device__ float g_lt[(size_t)BB * SEQ * DD];   // tf32(tanh(lt@W)*diag)
__device__ float g_rt[(size_t)BB * SEQ * DD];   // tf32(tanh(rt@W))
__device__ float g_wt[(size_t)DD * HH];         // tf32(W^T)  (D,H)

// ---------------------------------------------------------------------------
__device__ __forceinline__ uint32_t f2tf32(float f) {
    uint32_t r; asm("cvt.rna.tf32.f32 %0, %1;" : "=r"(r) : "f"(f)); return r;
}
__device__ __forceinline__ uint32_t smem_u32(const void* p) {
    uint32_t a;
    asm("{ .reg .u64 t; cvta.to.shared.u64 t, %1; cvt.u32.u64 %0, t; }" : "=r"(a) : "l"(p));
    return a;
}
__device__ __forceinline__ void cp16(uint32_t s, const void* g) {
    asm volatile("cp.async.cg.shared.global [%0], [%1], 16;" :: "r"(s), "l"(g));
}
#define CP_COMMIT() asm volatile("cp.async.commit_group;" ::: "memory")
#define CP_WAIT(n)  asm volatile("cp.async.wait_group %0;" :: "n"(n) : "memory")

__device__ __forceinline__ void ldsm_x4(uint32_t* r, uint32_t addr) {
    asm volatile("ldmatrix.sync.aligned.m8n8.x4.shared.b16 {%0,%1,%2,%3}, [%4];"
                 : "=r"(r[0]), "=r"(r[1]), "=r"(r[2]), "=r"(r[3]) : "r"(addr));
}
__device__ __forceinline__ void ldsm_x2(uint32_t* r, uint32_t addr) {
    asm volatile("ldmatrix.sync.aligned.m8n8.x2.shared.b16 {%0,%1}, [%2];"
                 : "=r"(r[0]), "=r"(r[1]) : "r"(addr));
}

// D[16x8] += A[16x8] * B[8x8]  (tf32, row.col; HW truncates fp32->tf32)
__device__ __forceinline__ void mma8(float* d, const uint32_t* a, const uint32_t* b) {
    asm volatile(
        "mma.sync.aligned.m16n8k8.row.col.f32.tf32.tf32.f32 "
        "{%0,%1,%2,%3}, {%4,%5,%6,%7}, {%8,%9}, {%0,%1,%2,%3};"
        : "+f"(d[0]), "+f"(d[1]), "+f"(d[2]), "+f"(d[3])
        : "r"(a[0]), "r"(a[1]), "r"(a[2]), "r"(a[3]), "r"(b[0]), "r"(b[1]));
}

#define PP 20                       // smem pitch: 16 data + 4 pad floats
#define PRJ_ASTG (128 * PP)         // proj A floats/stage
#define PRJ_BSTG (256 * PP)         // proj B floats/stage
#define PROJ_SMEM_BYTES (4 * (PRJ_ASTG + PRJ_BSTG) * 4)   // 122880

// ---------------------------------------------------------------------------
// Projection GEMM (lt and rt in one launch).
// CTA tile 128x256 (FULL N), K=512, BK=16, 4-stage cp.async ring.
// 8 warps (2M x 4N), warp tile 64x64; ldmatrix fragments.
// ---------------------------------------------------------------------------
__global__ __launch_bounds__(256, 1) void proj_tc(
    const float* __restrict__ lt, const float* __restrict__ rt,
    const float* __restrict__ diag,
    float* __restrict__ Clt, float* __restrict__ Crt)
{
    extern __shared__ float psm[];
    float* As = psm;                       // 4 x 128 x PP
    float* Bs = psm + 4 * PRJ_ASTG;        // 4 x 256 x PP

    const int tid = threadIdx.x, lane = tid & 31, wid = tid >> 5;
    const int gid = lane >> 2, tig = lane & 3;
    const int wm = wid & 1, wn = wid >> 1;

    const bool is_lt = blockIdx.x < 256;
    const int my = is_lt ? blockIdx.x : (blockIdx.x - 256);
    const float* A = (is_lt ? lt : rt) + (size_t)my * 128 * HH;
    float* C = (is_lt ? Clt : Crt) + (size_t)my * 128 * DD;

    float acc[4][8][4];
    #pragma unroll
    for (int mt = 0; mt < 4; mt++)
        #pragma unroll
        for (int nt = 0; nt < 8; nt++)
            #pragma unroll
            for (int c = 0; c < 4; c++) acc[mt][nt][c] = 0.f;

    // LDSM lane geometry
    const int rowin  = lane & 7;
    const int asel_r = (lane >> 3) & 1;
    const int asel_c = (lane >> 4) & 1;
    const int bsel_c = (lane >> 3) & 1;
    const uint32_t sA = smem_u32(As);
    const uint32_t sB = smem_u32(Bs);
    const uint32_t aoff0 = ((wm * 64 + asel_r * 8 + rowin) * PP + asel_c * 4) * 4;
    const uint32_t boff0 = ((wn * 64 + rowin) * PP + bsel_c * 4) * 4;
    const uint32_t ASTB = PRJ_ASTG * 4, BSTB = PRJ_BSTG * 4;

    // loaders: A: 2 thr/row x 2 cp16.  B: 1 thr/row x 4 cp16.
    const int ar_ld = tid >> 1;
    const int ah_ld = (tid & 1) * 8;
    auto load_tile = [&](int kt) {
        const int buf = kt & 3;
        const int kb = kt * 16;
        float* Ab = As + buf * PRJ_ASTG;
        float* Bb = Bs + buf * PRJ_BSTG;
        #pragma unroll
        for (int c = 0; c < 2; c++)
            cp16(smem_u32(&Ab[ar_ld * PP + ah_ld + c * 4]),
                 A + (size_t)ar_ld * HH + kb + ah_ld + c * 4);
        #pragma unroll
        for (int c = 0; c < 4; c++)
            cp16(smem_u32(&Bb[tid * PP + c * 4]),
                 g_wt + (size_t)tid * HH + kb + c * 4);
        CP_COMMIT();
    };

    constexpr int NK = HH / 16;   // 32
    load_tile(0); load_tile(1); load_tile(2);

    #pragma unroll 1
    for (int kt = 0; kt < NK; kt++) {
        CP_WAIT(2);
        __syncthreads();
        if (kt + 3 < NK) load_tile(kt + 3);

        const uint32_t abase = sA + (kt & 3) * ASTB + aoff0;
        const uint32_t bbase = sB + (kt & 3) * BSTB + boff0;
        #pragma unroll
        for (int ks = 0; ks < 2; ks++) {
            uint32_t af[4][4], bf[8][2];
            #pragma unroll
            for (int mt = 0; mt < 4; mt++)
                ldsm_x4(af[mt], abase + (mt * 16 * PP + ks * 8) * 4);
            #pragma unroll
            for (int nt = 0; nt < 8; nt++)
                ldsm_x2(bf[nt], bbase + (nt * 8 * PP + ks * 8) * 4);
            #pragma unroll
            for (int mt = 0; mt < 4; mt++)
                #pragma unroll
                for (int nt = 0; nt < 8; nt++)
                    mma8(acc[mt][nt], af[mt], bf[nt]);
        }
    }

    #pragma unroll
    for (int mt = 0; mt < 4; mt++) {
        const int row0 = wm * 64 + mt * 16 + gid;
        #pragma unroll
        for (int nt = 0; nt < 8; nt++) {
            const int col = wn * 64 + nt * 8 + tig * 2;
            float d0 = 1.f, d1 = 1.f;
            if (is_lt) { d0 = __ldg(diag + col); d1 = __ldg(diag + col + 1); }
            float2 v0, v1;
            v0.x = __uint_as_float(f2tf32(tanhf(acc[mt][nt][0]) * d0));
            v0.y = __uint_as_float(f2tf32(tanhf(acc[mt][nt][1]) * d1));
            v1.x = __uint_as_float(f2tf32(tanhf(acc[mt][nt][2]) * d0));
            v1.y = __uint_as_float(f2tf32(tanhf(acc[mt][nt][3]) * d1));
            *reinterpret_cast<float2*>(C + (size_t)row0 * DD + col) = v0;
            *reinterpret_cast<float2*>(C + (size_t)(row0 + 8) * DD + col) = v1;
        }
    }
}

// ---------------------------------------------------------------------------
// Fused scores + softmax, register-resident scores.
// CTA = 64 L-rows x full R=512, K=256, BK=32 (halved step count vs BK=16).
// grid = (SEQ/64, BB).
// ---------------------------------------------------------------------------
#define PA 260
#define PB2 36
#define FST2 (128 * PB2)
#define FS_SMEM_FLOATS (64 * PA + 4 * FST2 + 256 + 256)

__global__ __launch_bounds__(256, 1) void scores_softmax(float* __restrict__ out)
{
    extern __shared__ float sm[];
    float* Ar  = sm;                        // 64 x PA
    float* Bsm = sm + 64 * PA;              // 4 x 128 x PB2
    float* pm  = Bsm + 4 * FST2;            // 64 x 4 partial max
    float* ps  = pm + 256;                  // 64 x 4 partial sum

    const int tid = threadIdx.x, lane = tid & 31, wid = tid >> 5;
    const int gid = lane >> 2, tig = lane & 3;
    const int wm = wid & 1, wn = wid >> 1;
    const int b = blockIdx.y;

    const float* Lt = g_lt + (size_t)b * SEQ * DD + (size_t)blockIdx.x * 64 * DD;
    const float* Rt = g_rt + (size_t)b * SEQ * DD;

    // Resident A: 64 rows x 256 K; 4 threads/row x 16 float4 chunks
    {
        const int ar = tid >> 2;
        const int ch = tid & 3;
        #pragma unroll
        for (int it = 0; it < 16; it++) {
            const int col = ch * 4 + it * 16;
            cp16(smem_u32(&Ar[ar * PA + col]), Lt + (size_t)ar * DD + col);
        }
        CP_COMMIT();
    }

    // B loader: stage = 128 rows x 32 K; 2 thr/row x 4 cp16
    const int br_ld = tid >> 1;
    const int bh_ld = (tid & 1) * 16;
    auto load_b = [&](int j) {              // j = 0..31
        const int nc = j >> 3, kt = j & 7, buf = j & 3;
        const int kb = kt * 32;
        float* Bb = Bsm + buf * FST2;
        #pragma unroll
        for (int c = 0; c < 4; c++)
            cp16(smem_u32(&Bb[br_ld * PB2 + bh_ld + c * 4]),
                 Rt + (size_t)(nc * 128 + br_ld) * DD + kb + bh_ld + c * 4);
        CP_COMMIT();
    };

    // LDSM lane geometry
    const int rowin  = lane & 7;
    const int asel_r = (lane >> 3) & 1;
    const int asel_c = (lane >> 4) & 1;
    const int bsel_c = (lane >> 3) & 1;
    const uint32_t sAr = smem_u32(Ar);
    const uint32_t sBs = smem_u32(Bsm);
    const uint32_t aoff0 = ((wm * 32 + asel_r * 8 + rowin) * PA + asel_c * 4) * 4;
    const uint32_t boff0 = ((wn * 32 + rowin) * PB2 + bsel_c * 4) * 4;
    const uint32_t STB = FST2 * 4;

    load_b(0); load_b(1); load_b(2);

    float acc[4][2][4][4];                  // [nc][mt][nt][c]
    #pragma unroll
    for (int nc = 0; nc < 4; nc++)
        #pragma unroll
        for (int mt = 0; mt < 2; mt++)
            #pragma unroll
            for (int nt = 0; nt < 4; nt++)
                #pragma unroll
                for (int c = 0; c < 4; c++) acc[nc][mt][nt][c] = 0.f;

    #pragma unroll
    for (int nc = 0; nc < 4; nc++) {
        #pragma unroll 1
        for (int kt = 0; kt < 8; kt++) {
            const int i = nc * 8 + kt;
            CP_WAIT(2);
            __syncthreads();
            if (i + 3 < 32) load_b(i + 3);

            const uint32_t abase = sAr + aoff0 + (uint32_t)kt * 32 * 4;
            const uint32_t bbase = sBs + (uint32_t)(i & 3) * STB + boff0;
            #pragma unroll
            for (int ks = 0; ks < 4; ks++) {
                uint32_t af[2][4], bf[4][2];
                #pragma unroll
                for (int mt = 0; mt < 2; mt++)
                    ldsm_x4(af[mt], abase + (mt * 16 * PA + ks * 8) * 4);
                #pragma unroll
                for (int nt = 0; nt < 4; nt++)
                    ldsm_x2(bf[nt], bbase + (nt * 8 * PB2 + ks * 8) * 4);
                #pragma unroll
                for (int mt = 0; mt < 2; mt++)
                    #pragma unroll
                    for (int nt = 0; nt < 4; nt++)
                        mma8(acc[nc][mt][nt], af[mt], bf[nt]);
            }
        }
    }

    // ---- softmax on register-resident scores ----
    __syncthreads();

    float gm[2][2];
    #pragma unroll
    for (int mt = 0; mt < 2; mt++)
        #pragma unroll
        for (int d = 0; d < 2; d++) {
            float lm = -1e30f;
            #pragma unroll
            for (int nc = 0; nc < 4; nc++)
                #pragma unroll
                for (int nt = 0; nt < 4; nt++)
                    lm = fmaxf(lm, fmaxf(acc[nc][mt][nt][d * 2], acc[nc][mt][nt][d * 2 + 1]));
            lm = fmaxf(lm, __shfl_xor_sync(0xffffffffu, lm, 1));
            lm = fmaxf(lm, __shfl_xor_sync(0xffffffffu, lm, 2));
            const int row = wm * 32 + mt * 16 + d * 8 + gid;
            if (tig == 0) pm[row * 4 + wn] = lm;
        }
    __syncthreads();
    #pragma unroll
    for (int mt = 0; mt < 2; mt++)
        #pragma unroll
        for (int d = 0; d < 2; d++) {
            const int row = wm * 32 + mt * 16 + d * 8 + gid;
            gm[mt][d] = fmaxf(fmaxf(pm[row * 4 + 0], pm[row * 4 + 1]),
                              fmaxf(pm[row * 4 + 2], pm[row * 4 + 3]));
        }

    #pragma unroll
    for (int mt = 0; mt < 2; mt++)
        #pragma unroll
        for (int d = 0; d < 2; d++) {
            float lsum = 0.f;
            const float m = gm[mt][d];
            #pragma unroll
            for (int nc = 0; nc < 4; nc++)
                #pragma unroll
                for (int nt = 0; nt < 4; nt++) {
                    float e0 = __expf(acc[nc][mt][nt][d * 2]     - m);
                    float e1 = __expf(acc[nc][mt][nt][d * 2 + 1] - m);
                    acc[nc][mt][nt][d * 2]     = e0;
                    acc[nc][mt][nt][d * 2 + 1] = e1;
                    lsum += e0 + e1;
                }
            lsum += __shfl_xor_sync(0xffffffffu, lsum, 1);
            lsum += __shfl_xor_sync(0xffffffffu, lsum, 2);
            const int row = wm * 32 + mt * 16 + d * 8 + gid;
            if (tig == 0) ps[row * 4 + wn] = lsum;
        }
    __syncthreads();

    const size_t orow0 = ((size_t)b * SEQ + (size_t)blockIdx.x * 64);
    #pragma unroll
    for (int mt = 0; mt < 2; mt++)
        #pragma unroll
        for (int d = 0; d < 2; d++) {
            const int row = wm * 32 + mt * 16 + d * 8 + gid;
            const float inv = 1.f / (ps[row * 4 + 0] + ps[row * 4 + 1] +
                                     ps[row * 4 + 2] + ps[row * 4 + 3]);
            float* op = out + (orow0 + row) * SEQ;
            #pragma unroll
            for (int nc = 0; nc < 4; nc++)
                #pragma unroll
                for (int nt = 0; nt < 4; nt++) {
                    const int col = nc * 128 + wn * 32 + nt * 8 + tig * 2;
                    float2 v;
                    v.x = acc[nc][mt][nt][d * 2]     * inv;
                    v.y = acc[nc][mt][nt][d * 2 + 1] * inv;
                    *reinterpret_cast<float2*>(op + col) = v;
                }
        }
}

// ---------------------------------------------------------------------------
// W transpose (H,D) -> (D,H), pre-rounded to tf32.
// ---------------------------------------------------------------------------
__global__ void transpose_w(const float* __restrict__ W, float* __restrict__ Wt) {
    __shared__ float t[32][33];
    const int d0 = blockIdx.x * 32, h0 = blockIdx.y * 32;
    for (int i = threadIdx.y; i < 32; i += 8)
        t[i][threadIdx.x] = W[(size_t)(h0 + i) * DD + d0 + threadIdx.x];
    __syncthreads();
    for (int i = threadIdx.y; i < 32; i += 8)
        Wt[(size_t)(d0 + i) * HH + h0 + threadIdx.x] =
            __uint_as_float(f2tf32(t[threadIdx.x][i]));
}

// ---------------------------------------------------------------------------
extern "C" void kernel_launch(void* const* d_in, const int* in_sizes, int n_in,
                              void* d_out, int out_size)
{
    const float* lt = (const float*)d_in[0];   // (B, L, H)
    const float* rt = (const float*)d_in[1];   // (B, R, H)
    const float* W  = (const float*)d_in[2];   // (H, D)
    const float* dg = (const float*)d_in[3];   // (1, 1, D)
    float* out = (float*)d_out;                // (B, L, R)

    float *p_lt, *p_rt, *p_wt;
    cudaGetSymbolAddress((void**)&p_lt, g_lt);
    cudaGetSymbolAddress((void**)&p_rt, g_rt);
    cudaGetSymbolAddress((void**)&p_wt, g_wt);

    transpose_w<<<dim3(DD / 32, HH / 32), dim3(32, 8)>>>(W, p_wt);

    cudaFuncSetAttribute(proj_tc, cudaFuncAttributeMaxDynamicSharedMemorySize,
                         PROJ_SMEM_BYTES);
    proj_tc<<<512, 256, PROJ_SMEM_BYTES>>>(lt, rt, dg, p_lt, p_rt);

    const int FS_BYTES = FS_SMEM_FLOATS * 4;   // 143360
    cudaFuncSetAttribute(scores_softmax,
                         cudaFuncAttributeMaxDynamicSharedMemorySize, FS_BYTES);
    scores_softmax<<<dim3(SEQ / 64, BB), 256, FS_BYTES>>>(out);
}

// round 14
// speedup vs baseline: 1.6104x; 1.6104x over previous
#include <cuda_runtime.h>
#include <cuda_fp16.h>
#include <cstdint>
#include <math.h>

#define BB 64
#define SEQ 512
#define HH 512
#define DD 256

// Scratch (device globals; no allocs allowed in kernel_launch)
__device__ __half g_lt_in[(size_t)BB * SEQ * HH];  // fp16(lt)
__device__ __half g_rt_in[(size_t)BB * SEQ * HH];  // fp16(rt)
__device__ __half g_wt16[(size_t)DD * HH];         // fp16(W^T) (D,H)
__device__ __half g_lt16[(size_t)BB * SEQ * DD];   // fp16(tanh(lt@W)*diag)
__device__ __half g_rt16[(size_t)BB * SEQ * DD];   // fp16(tanh(rt@W))

// ---------------------------------------------------------------------------
__device__ __forceinline__ uint32_t smem_u32(const void* p) {
    uint32_t a;
    asm("{ .reg .u64 t; cvta.to.shared.u64 t, %1; cvt.u32.u64 %0, t; }" : "=r"(a) : "l"(p));
    return a;
}
__device__ __forceinline__ void cp16(uint32_t s, const void* g) {
    asm volatile("cp.async.cg.shared.global [%0], [%1], 16;" :: "r"(s), "l"(g));
}
#define CP_COMMIT() asm volatile("cp.async.commit_group;" ::: "memory")
#define CP_WAIT(n)  asm volatile("cp.async.wait_group %0;" :: "n"(n) : "memory")

__device__ __forceinline__ void ldsm_x4(uint32_t* r, uint32_t addr) {
    asm volatile("ldmatrix.sync.aligned.m8n8.x4.shared.b16 {%0,%1,%2,%3}, [%4];"
                 : "=r"(r[0]), "=r"(r[1]), "=r"(r[2]), "=r"(r[3]) : "r"(addr));
}
__device__ __forceinline__ void ldsm_x2(uint32_t* r, uint32_t addr) {
    asm volatile("ldmatrix.sync.aligned.m8n8.x2.shared.b16 {%0,%1}, [%2];"
                 : "=r"(r[0]), "=r"(r[1]) : "r"(addr));
}

// D[16x8] += A[16x16] * B[16x8]  (fp16 in, fp32 accum)
__device__ __forceinline__ void mma16(float* d, const uint32_t* a, const uint32_t* b) {
    asm volatile(
        "mma.sync.aligned.m16n8k16.row.col.f32.f16.f16.f32 "
        "{%0,%1,%2,%3}, {%4,%5,%6,%7}, {%8,%9}, {%0,%1,%2,%3};"
        : "+f"(d[0]), "+f"(d[1]), "+f"(d[2]), "+f"(d[3])
        : "r"(a[0]), "r"(a[1]), "r"(a[2]), "r"(a[3]), "r"(b[0]), "r"(b[1]));
}

#define PH 40                       // smem pitch in halfs: 32 data + 8 pad (80B)
#define PRJ_STG (128 * PH)          // halfs per matrix per stage
#define PROJ_SMEM_BYTES (4 * 2 * PRJ_STG * 2)   // 4 stages x (A+B) x 2B = 81920

// ---------------------------------------------------------------------------
// fp32 -> fp16 conversion prepass (lt and rt), float4 -> 2x half2
// ---------------------------------------------------------------------------
__global__ __launch_bounds__(256) void cvt_fp16(const float* __restrict__ in,
                                                __half* __restrict__ out, int n4) {
    int i = blockIdx.x * 256 + threadIdx.x;
    if (i < n4) {
        float4 v = reinterpret_cast<const float4*>(in)[i];
        __half2 h0 = __floats2half2_rn(v.x, v.y);
        __half2 h1 = __floats2half2_rn(v.z, v.w);
        uint2 u;
        u.x = *reinterpret_cast<uint32_t*>(&h0);
        u.y = *reinterpret_cast<uint32_t*>(&h1);
        reinterpret_cast<uint2*>(out)[i] = u;
    }
}

// W transpose (H,D) -> (D,H) fp16
__global__ void transpose_w(const float* __restrict__ W, __half* __restrict__ Wt) {
    __shared__ float t[32][33];
    const int d0 = blockIdx.x * 32, h0 = blockIdx.y * 32;
    for (int i = threadIdx.y; i < 32; i += 8)
        t[i][threadIdx.x] = W[(size_t)(h0 + i) * DD + d0 + threadIdx.x];
    __syncthreads();
    for (int i = threadIdx.y; i < 32; i += 8)
        Wt[(size_t)(d0 + i) * HH + h0 + threadIdx.x] = __float2half_rn(t[threadIdx.x][i]);
}

// ---------------------------------------------------------------------------
// Projection GEMM fp16 (lt and rt in one launch).
// CTA tile 128x128, K=512, BK=32 (16 steps), 4-stage cp.async ring, 1 sync/step.
// 8 warps (2Mx4N), warp tile 64x32, m16n8k16.
// ---------------------------------------------------------------------------
__global__ __launch_bounds__(256, 2) void proj_tc(const float* __restrict__ diag)
{
    extern __shared__ __half psm[];
    __half* As = psm;                      // 4 x 128 x PH
    __half* Bs = psm + 4 * PRJ_STG;        // 4 x 128 x PH

    const int tid = threadIdx.x, lane = tid & 31, wid = tid >> 5;
    const int gid = lane >> 2, tig = lane & 3;
    const int wm = wid & 1, wn = wid >> 1;

    const bool is_lt = blockIdx.y < 256;
    const int my = is_lt ? blockIdx.y : (blockIdx.y - 256);
    const __half* A = (is_lt ? g_lt_in : g_rt_in) + (size_t)my * 128 * HH;
    const __half* B = g_wt16 + (size_t)blockIdx.x * 128 * HH;
    __half* C = (is_lt ? g_lt16 : g_rt16) + (size_t)my * 128 * DD + blockIdx.x * 128;

    float acc[4][4][4];
    #pragma unroll
    for (int mt = 0; mt < 4; mt++)
        #pragma unroll
        for (int nt = 0; nt < 4; nt++)
            #pragma unroll
            for (int c = 0; c < 4; c++) acc[mt][nt][c] = 0.f;

    // LDSM lane geometry (byte offsets; half = 2B)
    const int rowin  = lane & 7;
    const int asel_r = (lane >> 3) & 1;       // +8 rows
    const int asel_c = (lane >> 4) & 1;       // +16B (8 halfs)
    const int bsel_c = (lane >> 3) & 1;       // +16B
    const uint32_t sA = smem_u32(As);
    const uint32_t sB = smem_u32(Bs);
    const uint32_t aoff0 = ((wm * 64 + asel_r * 8 + rowin) * PH + asel_c * 8) * 2;
    const uint32_t boff0 = ((wn * 32 + rowin) * PH + bsel_c * 8) * 2;
    const uint32_t STB = PRJ_STG * 2;         // stage bytes

    // loader: 2 thr/row; each 2 cp16 (32B = 16 halfs) for A and for B
    const int r_ld = tid >> 1;
    const int h_ld = (tid & 1) * 16;
    auto load_tile = [&](int kt) {
        const int buf = kt & 3;
        const int kb = kt * 32;
        __half* Ab = As + buf * PRJ_STG;
        __half* Bb = Bs + buf * PRJ_STG;
        #pragma unroll
        for (int c = 0; c < 2; c++) {
            cp16(smem_u32(&Ab[r_ld * PH + h_ld + c * 8]),
                 A + (size_t)r_ld * HH + kb + h_ld + c * 8);
            cp16(smem_u32(&Bb[r_ld * PH + h_ld + c * 8]),
                 B + (size_t)r_ld * HH + kb + h_ld + c * 8);
        }
        CP_COMMIT();
    };

    constexpr int NK = HH / 32;   // 16
    load_tile(0); load_tile(1); load_tile(2);

    #pragma unroll 1
    for (int kt = 0; kt < NK; kt++) {
        CP_WAIT(2);
        __syncthreads();
        if (kt + 3 < NK) load_tile(kt + 3);

        const uint32_t abase = sA + (kt & 3) * STB + aoff0;
        const uint32_t bbase = sB + (kt & 3) * STB + boff0;
        #pragma unroll
        for (int ks = 0; ks < 2; ks++) {      // two k16 halves of BK=32
            uint32_t af[4][4], bf[4][2];
            #pragma unroll
            for (int mt = 0; mt < 4; mt++)
                ldsm_x4(af[mt], abase + (mt * 16 * PH + ks * 16) * 2);
            #pragma unroll
            for (int nt = 0; nt < 4; nt++)
                ldsm_x2(bf[nt], bbase + (nt * 8 * PH + ks * 16) * 2);
            #pragma unroll
            for (int mt = 0; mt < 4; mt++)
                #pragma unroll
                for (int nt = 0; nt < 4; nt++)
                    mma16(acc[mt][nt], af[mt], bf[nt]);
        }
    }

    #pragma unroll
    for (int mt = 0; mt < 4; mt++) {
        const int row0 = wm * 64 + mt * 16 + gid;
        #pragma unroll
        for (int nt = 0; nt < 4; nt++) {
            const int col = wn * 32 + nt * 8 + tig * 2;
            float d0 = 1.f, d1 = 1.f;
            if (is_lt) {
                const int gcol = blockIdx.x * 128 + col;
                d0 = __ldg(diag + gcol); d1 = __ldg(diag + gcol + 1);
            }
            __half2 v0 = __floats2half2_rn(tanhf(acc[mt][nt][0]) * d0,
                                           tanhf(acc[mt][nt][1]) * d1);
            __half2 v1 = __floats2half2_rn(tanhf(acc[mt][nt][2]) * d0,
                                           tanhf(acc[mt][nt][3]) * d1);
            *reinterpret_cast<__half2*>(C + (size_t)row0 * DD + col) = v0;
            *reinterpret_cast<__half2*>(C + (size_t)(row0 + 8) * DD + col) = v1;
        }
    }
}

// ---------------------------------------------------------------------------
// Fused scores + softmax fp16, register-resident scores.
// CTA = 64 L-rows x full R=512, K=256, BK=32 (32 steps).  grid = (8, 64).
// ---------------------------------------------------------------------------
#define PAH 264                 // A pitch (halfs): 256 + 8 pad
#define FSTH (128 * PH)         // B halfs per stage
#define FS_SMEM_BYTES (64 * PAH * 2 + 4 * FSTH * 2 + 256 * 4 + 256 * 4)

__global__ __launch_bounds__(256, 1) void scores_softmax(float* __restrict__ out)
{
    extern __shared__ __half smh[];
    __half* Ar  = smh;                              // 64 x PAH
    __half* Bsm = smh + 64 * PAH;                   // 4 x 128 x PH
    float*  pm  = reinterpret_cast<float*>(Bsm + 4 * FSTH);   // 64 x 4
    float*  ps  = pm + 256;                                   // 64 x 4

    const int tid = threadIdx.x, lane = tid & 31, wid = tid >> 5;
    const int gid = lane >> 2, tig = lane & 3;
    const int wm = wid & 1, wn = wid >> 1;
    const int b = blockIdx.y;

    const __half* Lt = g_lt16 + (size_t)b * SEQ * DD + (size_t)blockIdx.x * 64 * DD;
    const __half* Rt = g_rt16 + (size_t)b * SEQ * DD;

    // Resident A: 64 rows x 256 halfs; 4 thr/row x 8 cp16 (128B each)
    {
        const int ar = tid >> 2;
        const int ch = tid & 3;
        #pragma unroll
        for (int it = 0; it < 8; it++) {
            const int colh = ch * 8 + it * 32;
            cp16(smem_u32(&Ar[ar * PAH + colh]), Lt + (size_t)ar * DD + colh);
        }
        CP_COMMIT();
    }

    // B loader: stage = 128 rows x 32 halfs; 2 thr/row x 2 cp16
    const int br_ld = tid >> 1;
    const int bh_ld = (tid & 1) * 16;
    auto load_b = [&](int j) {              // j = 0..31
        const int nc = j >> 3, kt = j & 7, buf = j & 3;
        const int kb = kt * 32;
        __half* Bb = Bsm + buf * FSTH;
        #pragma unroll
        for (int c = 0; c < 2; c++)
            cp16(smem_u32(&Bb[br_ld * PH + bh_ld + c * 8]),
                 Rt + (size_t)(nc * 128 + br_ld) * DD + kb + bh_ld + c * 8);
        CP_COMMIT();
    };

    // LDSM lane geometry
    const int rowin  = lane & 7;
    const int asel_r = (lane >> 3) & 1;
    const int asel_c = (lane >> 4) & 1;
    const int bsel_c = (lane >> 3) & 1;
    const uint32_t sAr = smem_u32(Ar);
    const uint32_t sBs = smem_u32(Bsm);
    const uint32_t aoff0 = ((wm * 32 + asel_r * 8 + rowin) * PAH + asel_c * 8) * 2;
    const uint32_t boff0 = ((wn * 32 + rowin) * PH + bsel_c * 8) * 2;
    const uint32_t STB = FSTH * 2;

    load_b(0); load_b(1); load_b(2);

    float acc[4][2][4][4];                  // [nc][mt][nt][c]
    #pragma unroll
    for (int nc = 0; nc < 4; nc++)
        #pragma unroll
        for (int mt = 0; mt < 2; mt++)
            #pragma unroll
            for (int nt = 0; nt < 4; nt++)
                #pragma unroll
                for (int c = 0; c < 4; c++) acc[nc][mt][nt][c] = 0.f;

    #pragma unroll
    for (int nc = 0; nc < 4; nc++) {
        #pragma unroll 1
        for (int kt = 0; kt < 8; kt++) {
            const int i = nc * 8 + kt;
            CP_WAIT(2);
            __syncthreads();
            if (i + 3 < 32) load_b(i + 3);

            const uint32_t abase = sAr + aoff0 + (uint32_t)kt * 32 * 2;
            const uint32_t bbase = sBs + (uint32_t)(i & 3) * STB + boff0;
            #pragma unroll
            for (int ks = 0; ks < 2; ks++) {
                uint32_t af[2][4], bf[4][2];
                #pragma unroll
                for (int mt = 0; mt < 2; mt++)
                    ldsm_x4(af[mt], abase + (mt * 16 * PAH + ks * 16) * 2);
                #pragma unroll
                for (int nt = 0; nt < 4; nt++)
                    ldsm_x2(bf[nt], bbase + (nt * 8 * PH + ks * 16) * 2);
                #pragma unroll
                for (int mt = 0; mt < 2; mt++)
                    #pragma unroll
                    for (int nt = 0; nt < 4; nt++)
                        mma16(acc[nc][mt][nt], af[mt], bf[nt]);
            }
        }
    }

    // ---- softmax on register-resident scores ----
    __syncthreads();

    float gm[2][2];
    #pragma unroll
    for (int mt = 0; mt < 2; mt++)
        #pragma unroll
        for (int d = 0; d < 2; d++) {
            float lm = -1e30f;
            #pragma unroll
            for (int nc = 0; nc < 4; nc++)
                #pragma unroll
                for (int nt = 0; nt < 4; nt++)
                    lm = fmaxf(lm, fmaxf(acc[nc][mt][nt][d * 2], acc[nc][mt][nt][d * 2 + 1]));
            lm = fmaxf(lm, __shfl_xor_sync(0xffffffffu, lm, 1));
            lm = fmaxf(lm, __shfl_xor_sync(0xffffffffu, lm, 2));
            const int row = wm * 32 + mt * 16 + d * 8 + gid;
            if (tig == 0) pm[row * 4 + wn] = lm;
        }
    __syncthreads();
    #pragma unroll
    for (int mt = 0; mt < 2; mt++)
        #pragma unroll
        for (int d = 0; d < 2; d++) {
            const int row = wm * 32 + mt * 16 + d * 8 + gid;
            gm[mt][d] = fmaxf(fmaxf(pm[row * 4 + 0], pm[row * 4 + 1]),
                              fmaxf(pm[row * 4 + 2], pm[row * 4 + 3]));
        }

    #pragma unroll
    for (int mt = 0; mt < 2; mt++)
        #pragma unroll
        for (int d = 0; d < 2; d++) {
            float lsum = 0.f;
            const float m = gm[mt][d];
            #pragma unroll
            for (int nc = 0; nc < 4; nc++)
                #pragma unroll
                for (int nt = 0; nt < 4; nt++) {
                    float e0 = __expf(acc[nc][mt][nt][d * 2]     - m);
                    float e1 = __expf(acc[nc][mt][nt][d * 2 + 1] - m);
                    acc[nc][mt][nt][d * 2]     = e0;
                    acc[nc][mt][nt][d * 2 + 1] = e1;
                    lsum += e0 + e1;
                }
            lsum += __shfl_xor_sync(0xffffffffu, lsum, 1);
            lsum += __shfl_xor_sync(0xffffffffu, lsum, 2);
            const int row = wm * 32 + mt * 16 + d * 8 + gid;
            if (tig == 0) ps[row * 4 + wn] = lsum;
        }
    __syncthreads();

    const size_t orow0 = ((size_t)b * SEQ + (size_t)blockIdx.x * 64);
    #pragma unroll
    for (int mt = 0; mt < 2; mt++)
        #pragma unroll
        for (int d = 0; d < 2; d++) {
            const int row = wm * 32 + mt * 16 + d * 8 + gid;
            const float inv = 1.f / (ps[row * 4 + 0] + ps[row * 4 + 1] +
                                     ps[row * 4 + 2] + ps[row * 4 + 3]);
            float* op = out + (orow0 + row) * SEQ;
            #pragma unroll
            for (int nc = 0; nc < 4; nc++)
                #pragma unroll
                for (int nt = 0; nt < 4; nt++) {
                    const int col = nc * 128 + wn * 32 + nt * 8 + tig * 2;
                    float2 v;
                    v.x = acc[nc][mt][nt][d * 2]     * inv;
                    v.y = acc[nc][mt][nt][d * 2 + 1] * inv;
                    *reinterpret_cast<float2*>(op + col) = v;
                }
        }
}

// ---------------------------------------------------------------------------
extern "C" void kernel_launch(void* const* d_in, const int* in_sizes, int n_in,
                              void* d_out, int out_size)
{
    const float* lt = (const float*)d_in[0];   // (B, L, H)
    const float* rt = (const float*)d_in[1];   // (B, R, H)
    const float* W  = (const float*)d_in[2];   // (H, D)
    const float* dg = (const float*)d_in[3];   // (1, 1, D)
    float* out = (float*)d_out;                // (B, L, R)

    __half *p_ltin, *p_rtin;
    cudaGetSymbolAddress((void**)&p_ltin, g_lt_in);
    cudaGetSymbolAddress((void**)&p_rtin, g_rt_in);
    __half *p_wt;
    cudaGetSymbolAddress((void**)&p_wt, g_wt16);

    const int n4 = (BB * SEQ * HH) / 4;        // 4.19M float4s
    cvt_fp16<<<(n4 + 255) / 256, 256>>>(lt, p_ltin, n4);
    cvt_fp16<<<(n4 + 255) / 256, 256>>>(rt, p_rtin, n4);
    transpose_w<<<dim3(DD / 32, HH / 32), dim3(32, 8)>>>(W, p_wt);

    cudaFuncSetAttribute(proj_tc, cudaFuncAttributeMaxDynamicSharedMemorySize,
                         PROJ_SMEM_BYTES);
    proj_tc<<<dim3(2, 512), 256, PROJ_SMEM_BYTES>>>(dg);

    cudaFuncSetAttribute(scores_softmax,
                         cudaFuncAttributeMaxDynamicSharedMemorySize, FS_SMEM_BYTES);
    scores_softmax<<<dim3(SEQ / 64, BB), 256, FS_SMEM_BYTES>>>(out);
}

// round 15
// speedup vs baseline: 1.6484x; 1.0236x over previous
#include <cuda_runtime.h>
#include <cuda_fp16.h>
#include <cstdint>
#include <math.h>

#define BB 64
#define SEQ 512
#define HH 512
#define DD 256

// Scratch (device globals; no allocs allowed in kernel_launch)
__device__ __half g_wt16[(size_t)DD * HH];         // fp16(W^T) (D,H)
__device__ __half g_lt16[(size_t)BB * SEQ * DD];   // fp16(tanh(lt@W)*diag)
__device__ __half g_rt16[(size_t)BB * SEQ * DD];   // fp16(tanh(rt@W))

// ---------------------------------------------------------------------------
__device__ __forceinline__ uint32_t smem_u32(const void* p) {
    uint32_t a;
    asm("{ .reg .u64 t; cvta.to.shared.u64 t, %1; cvt.u32.u64 %0, t; }" : "=r"(a) : "l"(p));
    return a;
}
__device__ __forceinline__ void cp16(uint32_t s, const void* g) {
    asm volatile("cp.async.cg.shared.global [%0], [%1], 16;" :: "r"(s), "l"(g));
}
#define CP_COMMIT() asm volatile("cp.async.commit_group;" ::: "memory")
#define CP_WAIT(n)  asm volatile("cp.async.wait_group %0;" :: "n"(n) : "memory")

__device__ __forceinline__ void ldsm_x4(uint32_t* r, uint32_t addr) {
    asm volatile("ldmatrix.sync.aligned.m8n8.x4.shared.b16 {%0,%1,%2,%3}, [%4];"
                 : "=r"(r[0]), "=r"(r[1]), "=r"(r[2]), "=r"(r[3]) : "r"(addr));
}
__device__ __forceinline__ void ldsm_x2(uint32_t* r, uint32_t addr) {
    asm volatile("ldmatrix.sync.aligned.m8n8.x2.shared.b16 {%0,%1}, [%2];"
                 : "=r"(r[0]), "=r"(r[1]) : "r"(addr));
}

// D[16x8] += A[16x16] * B[16x8]  (fp16 in, fp32 accum)
__device__ __forceinline__ void mma16(float* d, const uint32_t* a, const uint32_t* b) {
    asm volatile(
        "mma.sync.aligned.m16n8k16.row.col.f32.f16.f16.f32 "
        "{%0,%1,%2,%3}, {%4,%5,%6,%7}, {%8,%9}, {%0,%1,%2,%3};"
        : "+f"(d[0]), "+f"(d[1]), "+f"(d[2]), "+f"(d[3])
        : "r"(a[0]), "r"(a[1]), "r"(a[2]), "r"(a[3]), "r"(b[0]), "r"(b[1]));
}
__device__ __forceinline__ uint32_t packh2(float x, float y) {
    __half2 h = __floats2half2_rn(x, y);
    return *reinterpret_cast<uint32_t*>(&h);
}

#define PH  40                      // fp16 smem pitch (halfs): 32 data + 8 pad
#define PA4 40                      // fp32 A smem pitch (floats): 32 data + 8 pad
#define PRJ_ASTG (128 * PA4)        // A floats per stage
#define PRJ_BSTG (128 * PH)         // B halfs per stage
// 3 stages x (A fp32 + B fp16) = 3 x (20480 + 10240) = 92160 bytes
#define PROJ_SMEM_BYTES (3 * (PRJ_ASTG * 4 + PRJ_BSTG * 2))

// W transpose (H,D) -> (D,H) fp16
__global__ void transpose_w(const float* __restrict__ W, __half* __restrict__ Wt) {
    __shared__ float t[32][33];
    const int d0 = blockIdx.x * 32, h0 = blockIdx.y * 32;
    for (int i = threadIdx.y; i < 32; i += 8)
        t[i][threadIdx.x] = W[(size_t)(h0 + i) * DD + d0 + threadIdx.x];
    __syncthreads();
    for (int i = threadIdx.y; i < 32; i += 8)
        Wt[(size_t)(d0 + i) * HH + h0 + threadIdx.x] = __float2half_rn(t[threadIdx.x][i]);
}

// ---------------------------------------------------------------------------
// Projection GEMM, fused fp32->fp16 (A staged fp32, converted in-register).
// CTA tile 128x128, K=512, BK=32 (16 steps), 3-stage cp.async ring.
// 8 warps (2Mx4N), warp tile 64x32, m16n8k16.
// ---------------------------------------------------------------------------
__global__ __launch_bounds__(256, 2) void proj_tc(
    const float* __restrict__ lt, const float* __restrict__ rt,
    const float* __restrict__ diag)
{
    extern __shared__ float psm[];
    float*  As = psm;                                   // 3 x 128 x PA4 (fp32)
    __half* Bs = reinterpret_cast<__half*>(psm + 3 * PRJ_ASTG);  // 3 x 128 x PH

    const int tid = threadIdx.x, lane = tid & 31, wid = tid >> 5;
    const int gid = lane >> 2, tig = lane & 3;
    const int wm = wid & 1, wn = wid >> 1;

    const bool is_lt = blockIdx.y < 256;
    const int my = is_lt ? blockIdx.y : (blockIdx.y - 256);
    const float* A = (is_lt ? lt : rt) + (size_t)my * 128 * HH;
    const __half* B = g_wt16 + (size_t)blockIdx.x * 128 * HH;
    __half* C = (is_lt ? g_lt16 : g_rt16) + (size_t)my * 128 * DD + blockIdx.x * 128;

    float acc[4][4][4];
    #pragma unroll
    for (int mt = 0; mt < 4; mt++)
        #pragma unroll
        for (int nt = 0; nt < 4; nt++)
            #pragma unroll
            for (int c = 0; c < 4; c++) acc[mt][nt][c] = 0.f;

    // B LDSM lane geometry
    const int rowin  = lane & 7;
    const int bsel_c = (lane >> 3) & 1;
    const uint32_t sB = smem_u32(Bs);
    const uint32_t boff0 = ((wn * 32 + rowin) * PH + bsel_c * 8) * 2;
    const uint32_t BSTB = PRJ_BSTG * 2;

    // A loader: fp32, 2 thr/row, 16 floats (4 cp16) each
    const int ar_ld = tid >> 1;
    const int af_ld = (tid & 1) * 16;
    // B loader: fp16, 2 thr/row, 16 halfs (2 cp16) each
    auto load_tile = [&](int kt) {
        const int buf = kt % 3;
        const int kb = kt * 32;
        float*  Ab = As + buf * PRJ_ASTG;
        __half* Bb = Bs + buf * PRJ_BSTG;
        #pragma unroll
        for (int c = 0; c < 4; c++)
            cp16(smem_u32(&Ab[ar_ld * PA4 + af_ld + c * 4]),
                 A + (size_t)ar_ld * HH + kb + af_ld + c * 4);
        #pragma unroll
        for (int c = 0; c < 2; c++)
            cp16(smem_u32(&Bb[ar_ld * PH + (tid & 1) * 16 + c * 8]),
                 B + (size_t)ar_ld * HH + kb + (tid & 1) * 16 + c * 8);
        CP_COMMIT();
    };

    constexpr int NK = HH / 32;   // 16
    load_tile(0); load_tile(1);

    #pragma unroll 1
    for (int kt = 0; kt < NK; kt++) {
        CP_WAIT(1);
        __syncthreads();
        if (kt + 2 < NK) load_tile(kt + 2);

        const float* Ab = As + (kt % 3) * PRJ_ASTG;
        const uint32_t bbase = sB + (uint32_t)(kt % 3) * BSTB + boff0;
        #pragma unroll
        for (int ks = 0; ks < 2; ks++) {      // two k16 halves of BK=32
            uint32_t af[4][4], bf[4][2];
            const int k0 = ks * 16 + tig * 2;
            #pragma unroll
            for (int mt = 0; mt < 4; mt++) {
                const int r0 = (wm * 64 + mt * 16 + gid) * PA4;
                float2 x0 = *reinterpret_cast<const float2*>(Ab + r0 + k0);
                float2 x1 = *reinterpret_cast<const float2*>(Ab + r0 + 8 * PA4 + k0);
                float2 x2 = *reinterpret_cast<const float2*>(Ab + r0 + k0 + 8);
                float2 x3 = *reinterpret_cast<const float2*>(Ab + r0 + 8 * PA4 + k0 + 8);
                af[mt][0] = packh2(x0.x, x0.y);
                af[mt][1] = packh2(x1.x, x1.y);
                af[mt][2] = packh2(x2.x, x2.y);
                af[mt][3] = packh2(x3.x, x3.y);
            }
            #pragma unroll
            for (int nt = 0; nt < 4; nt++)
                ldsm_x2(bf[nt], bbase + (nt * 8 * PH + ks * 16) * 2);
            #pragma unroll
            for (int mt = 0; mt < 4; mt++)
                #pragma unroll
                for (int nt = 0; nt < 4; nt++)
                    mma16(acc[mt][nt], af[mt], bf[nt]);
        }
    }

    #pragma unroll
    for (int mt = 0; mt < 4; mt++) {
        const int row0 = wm * 64 + mt * 16 + gid;
        #pragma unroll
        for (int nt = 0; nt < 4; nt++) {
            const int col = wn * 32 + nt * 8 + tig * 2;
            float d0 = 1.f, d1 = 1.f;
            if (is_lt) {
                const int gcol = blockIdx.x * 128 + col;
                d0 = __ldg(diag + gcol); d1 = __ldg(diag + gcol + 1);
            }
            __half2 v0 = __floats2half2_rn(tanhf(acc[mt][nt][0]) * d0,
                                           tanhf(acc[mt][nt][1]) * d1);
            __half2 v1 = __floats2half2_rn(tanhf(acc[mt][nt][2]) * d0,
                                           tanhf(acc[mt][nt][3]) * d1);
            *reinterpret_cast<__half2*>(C + (size_t)row0 * DD + col) = v0;
            *reinterpret_cast<__half2*>(C + (size_t)(row0 + 8) * DD + col) = v1;
        }
    }
}

// ---------------------------------------------------------------------------
// Fused scores + softmax fp16, register-resident scores.
// CTA = 64 L-rows x full R=512, K=256, BK=32 (32 steps).  grid = (8, 64).
// ---------------------------------------------------------------------------
#define PAH 264                 // A pitch (halfs): 256 + 8 pad
#define FSTH (128 * PH)         // B halfs per stage
#define FS_SMEM_BYTES (64 * PAH * 2 + 4 * FSTH * 2 + 256 * 4 + 256 * 4)

__global__ __launch_bounds__(256, 1) void scores_softmax(float* __restrict__ out)
{
    extern __shared__ __half smh[];
    __half* Ar  = smh;                              // 64 x PAH
    __half* Bsm = smh + 64 * PAH;                   // 4 x 128 x PH
    float*  pm  = reinterpret_cast<float*>(Bsm + 4 * FSTH);   // 64 x 4
    float*  ps  = pm + 256;                                   // 64 x 4

    const int tid = threadIdx.x, lane = tid & 31, wid = tid >> 5;
    const int gid = lane >> 2, tig = lane & 3;
    const int wm = wid & 1, wn = wid >> 1;
    const int b = blockIdx.y;

    const __half* Lt = g_lt16 + (size_t)b * SEQ * DD + (size_t)blockIdx.x * 64 * DD;
    const __half* Rt = g_rt16 + (size_t)b * SEQ * DD;

    // Resident A: 64 rows x 256 halfs; 4 thr/row x 8 cp16
    {
        const int ar = tid >> 2;
        const int ch = tid & 3;
        #pragma unroll
        for (int it = 0; it < 8; it++) {
            const int colh = ch * 8 + it * 32;
            cp16(smem_u32(&Ar[ar * PAH + colh]), Lt + (size_t)ar * DD + colh);
        }
        CP_COMMIT();
    }

    // B loader: stage = 128 rows x 32 halfs; 2 thr/row x 2 cp16
    const int br_ld = tid >> 1;
    const int bh_ld = (tid & 1) * 16;
    auto load_b = [&](int j) {              // j = 0..31
        const int nc = j >> 3, kt = j & 7, buf = j & 3;
        const int kb = kt * 32;
        __half* Bb = Bsm + buf * FSTH;
        #pragma unroll
        for (int c = 0; c < 2; c++)
            cp16(smem_u32(&Bb[br_ld * PH + bh_ld + c * 8]),
                 Rt + (size_t)(nc * 128 + br_ld) * DD + kb + bh_ld + c * 8);
        CP_COMMIT();
    };

    // LDSM lane geometry
    const int rowin  = lane & 7;
    const int asel_r = (lane >> 3) & 1;
    const int asel_c = (lane >> 4) & 1;
    const int bsel_c = (lane >> 3) & 1;
    const uint32_t sAr = smem_u32(Ar);
    const uint32_t sBs = smem_u32(Bsm);
    const uint32_t aoff0 = ((wm * 32 + asel_r * 8 + rowin) * PAH + asel_c * 8) * 2;
    const uint32_t boff0 = ((wn * 32 + rowin) * PH + bsel_c * 8) * 2;
    const uint32_t STB = FSTH * 2;

    load_b(0); load_b(1); load_b(2);

    float acc[4][2][4][4];                  // [nc][mt][nt][c]
    #pragma unroll
    for (int nc = 0; nc < 4; nc++)
        #pragma unroll
        for (int mt = 0; mt < 2; mt++)
            #pragma unroll
            for (int nt = 0; nt < 4; nt++)
                #pragma unroll
                for (int c = 0; c < 4; c++) acc[nc][mt][nt][c] = 0.f;

    #pragma unroll
    for (int nc = 0; nc < 4; nc++) {
        #pragma unroll 1
        for (int kt = 0; kt < 8; kt++) {
            const int i = nc * 8 + kt;
            CP_WAIT(2);
            __syncthreads();
            if (i + 3 < 32) load_b(i + 3);

            const uint32_t abase = sAr + aoff0 + (uint32_t)kt * 32 * 2;
            const uint32_t bbase = sBs + (uint32_t)(i & 3) * STB + boff0;
            #pragma unroll
            for (int ks = 0; ks < 2; ks++) {
                uint32_t af[2][4], bf[4][2];
                #pragma unroll
                for (int mt = 0; mt < 2; mt++)
                    ldsm_x4(af[mt], abase + (mt * 16 * PAH + ks * 16) * 2);
                #pragma unroll
                for (int nt = 0; nt < 4; nt++)
                    ldsm_x2(bf[nt], bbase + (nt * 8 * PH + ks * 16) * 2);
                #pragma unroll
                for (int mt = 0; mt < 2; mt++)
                    #pragma unroll
                    for (int nt = 0; nt < 4; nt++)
                        mma16(acc[nc][mt][nt], af[mt], bf[nt]);
            }
        }
    }

    // ---- softmax on register-resident scores ----
    __syncthreads();

    float gm[2][2];
    #pragma unroll
    for (int mt = 0; mt < 2; mt++)
        #pragma unroll
        for (int d = 0; d < 2; d++) {
            float lm = -1e30f;
            #pragma unroll
            for (int nc = 0; nc < 4; nc++)
                #pragma unroll
                for (int nt = 0; nt < 4; nt++)
                    lm = fmaxf(lm, fmaxf(acc[nc][mt][nt][d * 2], acc[nc][mt][nt][d * 2 + 1]));
            lm = fmaxf(lm, __shfl_xor_sync(0xffffffffu, lm, 1));
            lm = fmaxf(lm, __shfl_xor_sync(0xffffffffu, lm, 2));
            const int row = wm * 32 + mt * 16 + d * 8 + gid;
            if (tig == 0) pm[row * 4 + wn] = lm;
        }
    __syncthreads();
    #pragma unroll
    for (int mt = 0; mt < 2; mt++)
        #pragma unroll
        for (int d = 0; d < 2; d++) {
            const int row = wm * 32 + mt * 16 + d * 8 + gid;
            gm[mt][d] = fmaxf(fmaxf(pm[row * 4 + 0], pm[row * 4 + 1]),
                              fmaxf(pm[row * 4 + 2], pm[row * 4 + 3]));
        }

    #pragma unroll
    for (int mt = 0; mt < 2; mt++)
        #pragma unroll
        for (int d = 0; d < 2; d++) {
            float lsum = 0.f;
            const float m = gm[mt][d];
            #pragma unroll
            for (int nc = 0; nc < 4; nc++)
                #pragma unroll
                for (int nt = 0; nt < 4; nt++) {
                    float e0 = __expf(acc[nc][mt][nt][d * 2]     - m);
                    float e1 = __expf(acc[nc][mt][nt][d * 2 + 1] - m);
                    acc[nc][mt][nt][d * 2]     = e0;
                    acc[nc][mt][nt][d * 2 + 1] = e1;
                    lsum += e0 + e1;
                }
            lsum += __shfl_xor_sync(0xffffffffu, lsum, 1);
            lsum += __shfl_xor_sync(0xffffffffu, lsum, 2);
            const int row = wm * 32 + mt * 16 + d * 8 + gid;
            if (tig == 0) ps[row * 4 + wn] = lsum;
        }
    __syncthreads();

    const size_t orow0 = ((size_t)b * SEQ + (size_t)blockIdx.x * 64);
    #pragma unroll
    for (int mt = 0; mt < 2; mt++)
        #pragma unroll
        for (int d = 0; d < 2; d++) {
            const int row = wm * 32 + mt * 16 + d * 8 + gid;
            const float inv = 1.f / (ps[row * 4 + 0] + ps[row * 4 + 1] +
                                     ps[row * 4 + 2] + ps[row * 4 + 3]);
            float* op = out + (orow0 + row) * SEQ;
            #pragma unroll
            for (int nc = 0; nc < 4; nc++)
                #pragma unroll
                for (int nt = 0; nt < 4; nt++) {
                    const int col = nc * 128 + wn * 32 + nt * 8 + tig * 2;
                    float2 v;
                    v.x = acc[nc][mt][nt][d * 2]     * inv;
                    v.y = acc[nc][mt][nt][d * 2 + 1] * inv;
                    *reinterpret_cast<float2*>(op + col) = v;
                }
        }
}

// ---------------------------------------------------------------------------
extern "C" void kernel_launch(void* const* d_in, const int* in_sizes, int n_in,
                              void* d_out, int out_size)
{
    const float* lt = (const float*)d_in[0];   // (B, L, H)
    const float* rt = (const float*)d_in[1];   // (B, R, H)
    const float* W  = (const float*)d_in[2];   // (H, D)
    const float* dg = (const float*)d_in[3];   // (1, 1, D)
    float* out = (float*)d_out;                // (B, L, R)

    __half* p_wt;
    cudaGetSymbolAddress((void**)&p_wt, g_wt16);

    transpose_w<<<dim3(DD / 32, HH / 32), dim3(32, 8)>>>(W, p_wt);

    cudaFuncSetAttribute(proj_tc, cudaFuncAttributeMaxDynamicSharedMemorySize,
                         PROJ_SMEM_BYTES);
    proj_tc<<<dim3(2, 512), 256, PROJ_SMEM_BYTES>>>(lt, rt, dg);

    cudaFuncSetAttribute(scores_softmax,
                         cudaFuncAttributeMaxDynamicSharedMemorySize, FS_SMEM_BYTES);
    scores_softmax<<<dim3(SEQ / 64, BB), 256, FS_SMEM_BYTES>>>(out);
}

// round 17
// speedup vs baseline: 1.8950x; 1.1496x over previous
#include <cuda_runtime.h>
#include <cuda_fp16.h>
#include <cstdint>
#include <math.h>

#define BB 64
#define SEQ 512
#define HH 512
#define DD 256

// Scratch (device globals; no allocs allowed in kernel_launch)
__device__ __half g_wt16[(size_t)DD * HH];         // fp16(W^T) (D,H)
__device__ __half g_lt16[(size_t)BB * SEQ * DD];   // fp16(tanh(lt@W)*diag)
__device__ __half g_rt16[(size_t)BB * SEQ * DD];   // fp16(tanh(rt@W))

// ---------------------------------------------------------------------------
__device__ __forceinline__ uint32_t smem_u32(const void* p) {
    uint32_t a;
    asm("{ .reg .u64 t; cvta.to.shared.u64 t, %1; cvt.u32.u64 %0, t; }" : "=r"(a) : "l"(p));
    return a;
}
__device__ __forceinline__ void cp16(uint32_t s, const void* g) {
    asm volatile("cp.async.cg.shared.global [%0], [%1], 16;" :: "r"(s), "l"(g));
}
#define CP_COMMIT() asm volatile("cp.async.commit_group;" ::: "memory")
#define CP_WAIT(n)  asm volatile("cp.async.wait_group %0;" :: "n"(n) : "memory")

__device__ __forceinline__ void ldsm_x4(uint32_t* r, uint32_t addr) {
    asm volatile("ldmatrix.sync.aligned.m8n8.x4.shared.b16 {%0,%1,%2,%3}, [%4];"
                 : "=r"(r[0]), "=r"(r[1]), "=r"(r[2]), "=r"(r[3]) : "r"(addr));
}
__device__ __forceinline__ void ldsm_x2(uint32_t* r, uint32_t addr) {
    asm volatile("ldmatrix.sync.aligned.m8n8.x2.shared.b16 {%0,%1}, [%2];"
                 : "=r"(r[0]), "=r"(r[1]) : "r"(addr));
}

// D[16x8] += A[16x16] * B[16x8]  (fp16 in, fp32 accum)
__device__ __forceinline__ void mma16(float* d, const uint32_t* a, const uint32_t* b) {
    asm volatile(
        "mma.sync.aligned.m16n8k16.row.col.f32.f16.f16.f32 "
        "{%0,%1,%2,%3}, {%4,%5,%6,%7}, {%8,%9}, {%0,%1,%2,%3};"
        : "+f"(d[0]), "+f"(d[1]), "+f"(d[2]), "+f"(d[3])
        : "r"(a[0]), "r"(a[1]), "r"(a[2]), "r"(a[3]), "r"(b[0]), "r"(b[1]));
}
__device__ __forceinline__ uint32_t packh2(float x, float y) {
    __half2 h = __floats2half2_rn(x, y);
    return *reinterpret_cast<uint32_t*>(&h);
}

#define PH  40                      // fp16 smem pitch (halfs): 32 data + 8 pad
#define PRJ_STG (128 * PH)          // halfs per matrix per stage
// 3 stages x (A fp16 + B fp16) = 3 x (10240 + 10240) = 61440 bytes
#define PROJ_SMEM_BYTES (3 * 2 * PRJ_STG * 2)

// W transpose (H,D) -> (D,H) fp16
__global__ void transpose_w(const float* __restrict__ W, __half* __restrict__ Wt) {
    __shared__ float t[32][33];
    const int d0 = blockIdx.x * 32, h0 = blockIdx.y * 32;
    for (int i = threadIdx.y; i < 32; i += 8)
        t[i][threadIdx.x] = W[(size_t)(h0 + i) * DD + d0 + threadIdx.x];
    __syncthreads();
    for (int i = threadIdx.y; i < 32; i += 8)
        Wt[(size_t)(d0 + i) * HH + h0 + threadIdx.x] = __float2half_rn(t[threadIdx.x][i]);
}

// ---------------------------------------------------------------------------
// Projection GEMM; A converted fp32->fp16 in the LOADER (LDG+cvt+STS,
// software-pipelined one iteration ahead).  B via cp.async fp16.
// CTA tile 128x128, K=512, BK=32 (16 steps), 3-stage ring, 1 sync/step.
// 8 warps (2Mx4N), warp tile 64x32, m16n8k16, ldmatrix fragments.
// ---------------------------------------------------------------------------
__global__ __launch_bounds__(256, 2) void proj_tc(
    const float* __restrict__ lt, const float* __restrict__ rt,
    const float* __restrict__ diag)
{
    extern __shared__ __half psm[];
    __half* As = psm;                      // 3 x 128 x PH
    __half* Bs = psm + 3 * PRJ_STG;        // 3 x 128 x PH

    const int tid = threadIdx.x, lane = tid & 31, wid = tid >> 5;
    const int gid = lane >> 2, tig = lane & 3;
    const int wm = wid & 1, wn = wid >> 1;

    const bool is_lt = blockIdx.y < 256;
    const int my = is_lt ? blockIdx.y : (blockIdx.y - 256);
    const float* A = (is_lt ? lt : rt) + (size_t)my * 128 * HH;
    const __half* B = g_wt16 + (size_t)blockIdx.x * 128 * HH;
    __half* C = (is_lt ? g_lt16 : g_rt16) + (size_t)my * 128 * DD + blockIdx.x * 128;

    float acc[4][4][4];
    #pragma unroll
    for (int mt = 0; mt < 4; mt++)
        #pragma unroll
        for (int nt = 0; nt < 4; nt++)
            #pragma unroll
            for (int c = 0; c < 4; c++) acc[mt][nt][c] = 0.f;

    // LDSM lane geometry
    const int rowin  = lane & 7;
    const int asel_r = (lane >> 3) & 1;
    const int bsel_c = (lane >> 3) & 1;
    const int asel_c = (lane >> 4) & 1;
    const uint32_t sA = smem_u32(As);
    const uint32_t sB = smem_u32(Bs);
    const uint32_t aoff0 = ((wm * 64 + asel_r * 8 + rowin) * PH + asel_c * 8) * 2;
    const uint32_t boff0 = ((wn * 32 + rowin) * PH + bsel_c * 8) * 2;
    const uint32_t STB = PRJ_STG * 2;      // stage bytes

    // Loader mapping: 2 thr/row; thread covers 16 elements at col (tid&1)*16.
    const int r_ld = tid >> 1;
    const int h_ld = (tid & 1) * 16;
    const float* Arow = A + (size_t)r_ld * HH + h_ld;
    const __half* Brow = B + (size_t)r_ld * HH + h_ld;

    // A gmem fetch (fp32) into regs
    float4 abuf[4];
    auto ldg_a = [&](int kt) {
        #pragma unroll
        for (int c = 0; c < 4; c++)
            abuf[c] = *reinterpret_cast<const float4*>(Arow + kt * 32 + c * 4);
    };
    // cvt + store A regs into smem stage
    auto sts_a = [&](int kt) {
        __half* Ab = As + (kt % 3) * PRJ_STG + r_ld * PH + h_ld;
        uint4 u0, u1;
        u0.x = packh2(abuf[0].x, abuf[0].y); u0.y = packh2(abuf[0].z, abuf[0].w);
        u0.z = packh2(abuf[1].x, abuf[1].y); u0.w = packh2(abuf[1].z, abuf[1].w);
        u1.x = packh2(abuf[2].x, abuf[2].y); u1.y = packh2(abuf[2].z, abuf[2].w);
        u1.z = packh2(abuf[3].x, abuf[3].y); u1.w = packh2(abuf[3].z, abuf[3].w);
        *reinterpret_cast<uint4*>(Ab)     = u0;
        *reinterpret_cast<uint4*>(Ab + 8) = u1;
    };
    auto cp_b = [&](int kt) {
        __half* Bb = Bs + (kt % 3) * PRJ_STG + r_ld * PH + h_ld;
        cp16(smem_u32(Bb),     Brow + kt * 32);
        cp16(smem_u32(Bb + 8), Brow + kt * 32 + 8);
        CP_COMMIT();
    };

    constexpr int NK = HH / 32;   // 16

    // Prologue: A0 straight to smem; A1 into regs; B0,B1 in flight.
    ldg_a(0); sts_a(0);
    cp_b(0);
    ldg_a(1);
    cp_b(1);

    #pragma unroll 1
    for (int kt = 0; kt < NK; kt++) {
        CP_WAIT(1);
        __syncthreads();
        // stage kt+1: cvt+store regs (loaded last iteration)
        if (kt + 1 < NK) sts_a(kt + 1);
        // stage kt+2: issue new loads
        if (kt + 2 < NK) { ldg_a(kt + 2); cp_b(kt + 2); }

        const uint32_t abase = sA + (uint32_t)(kt % 3) * STB + aoff0;
        const uint32_t bbase = sB + (uint32_t)(kt % 3) * STB + boff0;
        #pragma unroll
        for (int ks = 0; ks < 2; ks++) {
            uint32_t af[4][4], bf[4][2];
            #pragma unroll
            for (int mt = 0; mt < 4; mt++)
                ldsm_x4(af[mt], abase + (mt * 16 * PH + ks * 16) * 2);
            #pragma unroll
            for (int nt = 0; nt < 4; nt++)
                ldsm_x2(bf[nt], bbase + (nt * 8 * PH + ks * 16) * 2);
            #pragma unroll
            for (int mt = 0; mt < 4; mt++)
                #pragma unroll
                for (int nt = 0; nt < 4; nt++)
                    mma16(acc[mt][nt], af[mt], bf[nt]);
        }
    }

    #pragma unroll
    for (int mt = 0; mt < 4; mt++) {
        const int row0 = wm * 64 + mt * 16 + gid;
        #pragma unroll
        for (int nt = 0; nt < 4; nt++) {
            const int col = wn * 32 + nt * 8 + tig * 2;
            float d0 = 1.f, d1 = 1.f;
            if (is_lt) {
                const int gcol = blockIdx.x * 128 + col;
                d0 = __ldg(diag + gcol); d1 = __ldg(diag + gcol + 1);
            }
            __half2 v0 = __floats2half2_rn(tanhf(acc[mt][nt][0]) * d0,
                                           tanhf(acc[mt][nt][1]) * d1);
            __half2 v1 = __floats2half2_rn(tanhf(acc[mt][nt][2]) * d0,
                                           tanhf(acc[mt][nt][3]) * d1);
            *reinterpret_cast<__half2*>(C + (size_t)row0 * DD + col) = v0;
            *reinterpret_cast<__half2*>(C + (size_t)(row0 + 8) * DD + col) = v1;
        }
    }
}

// ---------------------------------------------------------------------------
// Fused scores + softmax fp16, register-resident scores.
// CTA = 64 L-rows x full R=512, K=256, BK=32 (32 steps).  grid = (8, 64).
// ---------------------------------------------------------------------------
#define PAH 264                 // A pitch (halfs): 256 + 8 pad
#define FSTH (128 * PH)         // B halfs per stage
#define FS_SMEM_BYTES (64 * PAH * 2 + 4 * FSTH * 2 + 256 * 4 + 256 * 4)

__global__ __launch_bounds__(256, 1) void scores_softmax(float* __restrict__ out)
{
    extern __shared__ __half smh[];
    __half* Ar  = smh;                              // 64 x PAH
    __half* Bsm = smh + 64 * PAH;                   // 4 x 128 x PH
    float*  pm  = reinterpret_cast<float*>(Bsm + 4 * FSTH);   // 64 x 4
    float*  ps  = pm + 256;                                   // 64 x 4

    const int tid = threadIdx.x, lane = tid & 31, wid = tid >> 5;
    const int gid = lane >> 2, tig = lane & 3;
    const int wm = wid & 1, wn = wid >> 1;
    const int b = blockIdx.y;

    const __half* Lt = g_lt16 + (size_t)b * SEQ * DD + (size_t)blockIdx.x * 64 * DD;
    const __half* Rt = g_rt16 + (size_t)b * SEQ * DD;

    // Resident A: 64 rows x 256 halfs; 4 thr/row x 8 cp16
    {
        const int ar = tid >> 2;
        const int ch = tid & 3;
        #pragma unroll
        for (int it = 0; it < 8; it++) {
            const int colh = ch * 8 + it * 32;
            cp16(smem_u32(&Ar[ar * PAH + colh]), Lt + (size_t)ar * DD + colh);
        }
        CP_COMMIT();
    }

    // B loader: stage = 128 rows x 32 halfs; 2 thr/row x 2 cp16
    const int br_ld = tid >> 1;
    const int bh_ld = (tid & 1) * 16;
    auto load_b = [&](int j) {              // j = 0..31
        const int nc = j >> 3, kt = j & 7, buf = j & 3;
        const int kb = kt * 32;
        __half* Bb = Bsm + buf * FSTH;
        #pragma unroll
        for (int c = 0; c < 2; c++)
            cp16(smem_u32(&Bb[br_ld * PH + bh_ld + c * 8]),
                 Rt + (size_t)(nc * 128 + br_ld) * DD + kb + bh_ld + c * 8);
        CP_COMMIT();
    };

    // LDSM lane geometry
    const int rowin  = lane & 7;
    const int asel_r = (lane >> 3) & 1;
    const int asel_c = (lane >> 4) & 1;
    const int bsel_c = (lane >> 3) & 1;
    const uint32_t sAr = smem_u32(Ar);
    const uint32_t sBs = smem_u32(Bsm);
    const uint32_t aoff0 = ((wm * 32 + asel_r * 8 + rowin) * PAH + asel_c * 8) * 2;
    const uint32_t boff0 = ((wn * 32 + rowin) * PH + bsel_c * 8) * 2;
    const uint32_t STB = FSTH * 2;

    load_b(0); load_b(1); load_b(2);

    float acc[4][2][4][4];                  // [nc][mt][nt][c]
    #pragma unroll
    for (int nc = 0; nc < 4; nc++)
        #pragma unroll
        for (int mt = 0; mt < 2; mt++)
            #pragma unroll
            for (int nt = 0; nt < 4; nt++)
                #pragma unroll
                for (int c = 0; c < 4; c++) acc[nc][mt][nt][c] = 0.f;

    #pragma unroll
    for (int nc = 0; nc < 4; nc++) {
        #pragma unroll 1
        for (int kt = 0; kt < 8; kt++) {
            const int i = nc * 8 + kt;
            CP_WAIT(2);
            __syncthreads();
            if (i + 3 < 32) load_b(i + 3);

            const uint32_t abase = sAr + aoff0 + (uint32_t)kt * 32 * 2;
            const uint32_t bbase = sBs + (uint32_t)(i & 3) * STB + boff0;
            #pragma unroll
            for (int ks = 0; ks < 2; ks++) {
                uint32_t af[2][4], bf[4][2];
                #pragma unroll
                for (int mt = 0; mt < 2; mt++)
                    ldsm_x4(af[mt], abase + (mt * 16 * PAH + ks * 16) * 2);
                #pragma unroll
                for (int nt = 0; nt < 4; nt++)
                    ldsm_x2(bf[nt], bbase + (nt * 8 * PH + ks * 16) * 2);
                #pragma unroll
                for (int mt = 0; mt < 2; mt++)
                    #pragma unroll
                    for (int nt = 0; nt < 4; nt++)
                        mma16(acc[nc][mt][nt], af[mt], bf[nt]);
            }
        }
    }

    // ---- softmax on register-resident scores ----
    __syncthreads();

    float gm[2][2];
    #pragma unroll
    for (int mt = 0; mt < 2; mt++)
        #pragma unroll
        for (int d = 0; d < 2; d++) {
            float lm = -1e30f;
            #pragma unroll
            for (int nc = 0; nc < 4; nc++)
                #pragma unroll
                for (int nt = 0; nt < 4; nt++)
                    lm = fmaxf(lm, fmaxf(acc[nc][mt][nt][d * 2], acc[nc][mt][nt][d * 2 + 1]));
            lm = fmaxf(lm, __shfl_xor_sync(0xffffffffu, lm, 1));
            lm = fmaxf(lm, __shfl_xor_sync(0xffffffffu, lm, 2));
            const int row = wm * 32 + mt * 16 + d * 8 + gid;
            if (tig == 0) pm[row * 4 + wn] = lm;
        }
    __syncthreads();
    #pragma unroll
    for (int mt = 0; mt < 2; mt++)
        #pragma unroll
        for (int d = 0; d < 2; d++) {
            const int row = wm * 32 + mt * 16 + d * 8 + gid;
            gm[mt][d] = fmaxf(fmaxf(pm[row * 4 + 0], pm[row * 4 + 1]),
                              fmaxf(pm[row * 4 + 2], pm[row * 4 + 3]));
        }

    #pragma unroll
    for (int mt = 0; mt < 2; mt++)
        #pragma unroll
        for (int d = 0; d < 2; d++) {
            float lsum = 0.f;
            const float m = gm[mt][d];
            #pragma unroll
            for (int nc = 0; nc < 4; nc++)
                #pragma unroll
                for (int nt = 0; nt < 4; nt++) {
                    float e0 = __expf(acc[nc][mt][nt][d * 2]     - m);
                    float e1 = __expf(acc[nc][mt][nt][d * 2 + 1] - m);
                    acc[nc][mt][nt][d * 2]     = e0;
                    acc[nc][mt][nt][d * 2 + 1] = e1;
                    lsum += e0 + e1;
                }
            lsum += __shfl_xor_sync(0xffffffffu, lsum, 1);
            lsum += __shfl_xor_sync(0xffffffffu, lsum, 2);
            const int row = wm * 32 + mt * 16 + d * 8 + gid;
            if (tig == 0) ps[row * 4 + wn] = lsum;
        }
    __syncthreads();

    const size_t orow0 = ((size_t)b * SEQ + (size_t)blockIdx.x * 64);
    #pragma unroll
    for (int mt = 0; mt < 2; mt++)
        #pragma unroll
        for (int d = 0; d < 2; d++) {
            const int row = wm * 32 + mt * 16 + d * 8 + gid;
            const float inv = 1.f / (ps[row * 4 + 0] + ps[row * 4 + 1] +
                                     ps[row * 4 + 2] + ps[row * 4 + 3]);
            float* op = out + (orow0 + row) * SEQ;
            #pragma unroll
            for (int nc = 0; nc < 4; nc++)
                #pragma unroll
                for (int nt = 0; nt < 4; nt++) {
                    const int col = nc * 128 + wn * 32 + nt * 8 + tig * 2;
                    float2 v;
                    v.x = acc[nc][mt][nt][d * 2]     * inv;
                    v.y = acc[nc][mt][nt][d * 2 + 1] * inv;
                    *reinterpret_cast<float2*>(op + col) = v;
                }
        }
}

// ---------------------------------------------------------------------------
extern "C" void kernel_launch(void* const* d_in, const int* in_sizes, int n_in,
                              void* d_out, int out_size)
{
    const float* lt = (const float*)d_in[0];   // (B, L, H)
    const float* rt = (const float*)d_in[1];   // (B, R, H)
    const float* W  = (const float*)d_in[2];   // (H, D)
    const float* dg = (const float*)d_in[3];   // (1, 1, D)
    float* out = (float*)d_out;                // (B, L, R)

    __half* p_wt;
    cudaGetSymbolAddress((void**)&p_wt, g_wt16);

    transpose_w<<<dim3(DD / 32, HH / 32), dim3(32, 8)>>>(W, p_wt);

    cudaFuncSetAttribute(proj_tc, cudaFuncAttributeMaxDynamicSharedMemorySize,
                         PROJ_SMEM_BYTES);
    proj_tc<<<dim3(2, 512), 256, PROJ_SMEM_BYTES>>>(lt, rt, dg);

    cudaFuncSetAttribute(scores_softmax,
                         cudaFuncAttributeMaxDynamicSharedMemorySize, FS_SMEM_BYTES);
    scores_softmax<<<dim3(SEQ / 64, BB), 256, FS_SMEM_BYTES>>>(out);
}